// round 12
// baseline (speedup 1.0000x reference)
#include <cuda_runtime.h>
#include <cstdint>

// Problem constants
#define BATCH 8
#define HH 384
#define WW 384
#define PHI 32
#define RHO 64
#define Q_SCALE (255.0f / 32.0f)

#define TY 8
#define TX 384          // full image width: 12KB contiguous per plane per block

// ---------------------------------------------------------------------------
// f32x2 packed helpers (sm_103a)
// ---------------------------------------------------------------------------
__device__ __forceinline__ unsigned long long ffma2(unsigned long long a,
                                                    unsigned long long b,
                                                    unsigned long long c) {
    unsigned long long d;
    asm("fma.rn.f32x2 %0, %1, %2, %3;" : "=l"(d) : "l"(a), "l"(b), "l"(c));
    return d;
}
__device__ __forceinline__ unsigned long long pack_dup(float v) {
    unsigned long long d;
    asm("mov.b64 %0, {%1, %1};" : "=l"(d) : "f"(v));
    return d;
}
__device__ __forceinline__ unsigned long long pack2(float lo, float hi) {
    unsigned long long d;
    asm("mov.b64 %0, {%1, %2};" : "=l"(d) : "f"(lo), "f"(hi));
    return d;
}
__device__ __forceinline__ void unpack2(unsigned long long a, float& lo, float& hi) {
    asm("mov.b64 {%0, %1}, %2;" : "=f"(lo), "=f"(hi) : "l"(a));
}

// ---------------------------------------------------------------------------
// Fused kernel (R8 core, full-width tiles).
//   q = floor(x*255/32) in {0..7}; MLP collapses to 8x64 LUT
//   u[l][c] = ((relu(l*w1+b1) @ w2 + b2) @ w3) / 9.
//   out[c] = relu( sum_{l=1..7} n_l*(u[l][c]-u[0][c]) + (b3[c]+9*u[0][c]) )
//   Count->float: bits (n | 0x4B000000) = 2^23 + n, subtract 2^23 (exact).
// Tile = full W x 8 rows: each block writes 12KB CONTIGUOUS per (b,c) plane.
// Grid = 384 blocks <= 444 resident slots at occ-3: single wave, no tail.
// ---------------------------------------------------------------------------
__global__ __launch_bounds__(256, 3)
void lpmp_fused(const float* __restrict__ x,
                const float* __restrict__ w1, const float* __restrict__ b1,
                const float* __restrict__ w2, const float* __restrict__ b2,
                const float* __restrict__ w3, const float* __restrict__ b3,
                float* __restrict__ out) {
    __shared__ float h2S[8][PHI];        // hidden layer per level
    __shared__ float uRaw[8][RHO];       // raw LUT
    __shared__ float uS[7][RHO];         // u[l]-u[0]
    __shared__ float biasS[RHO];         // b3 + 9*u[0]
    __shared__ uint32_t rs[TY + 2][TX];  // horizontal one-hot 3-sums
    __shared__ uint32_t pk[TY][TX];      // 3x3 packed nibble counts

    const int y0 = blockIdx.x * TY;
    const int b  = blockIdx.y;
    const int tid = threadIdx.y * 32 + threadIdx.x;
    const float* xb = x + (size_t)b * HH * WW;

    // ---- Phase 0a: h2[l][d] = b2[d] + sum_j relu(l*w1[j]+b1[j]) * w2[j][d] ----
    {
        int l = tid >> 5;            // 0..7
        int d = tid & 31;            // 0..31
        float acc = b2[d];
        float lf = (float)l;
#pragma unroll
        for (int j = 0; j < PHI; j++) {
            float h1 = fmaxf(fmaf(lf, w1[j], b1[j]), 0.0f);
            acc = fmaf(h1, w2[j * PHI + d], acc);
        }
        h2S[l][d] = acc;
    }
    __syncthreads();

    // ---- Phase 0b: uRaw[l][c] = (h2[l] . w3[:,c]) / 9, 512 entries ----
#pragma unroll
    for (int e = 0; e < 2; e++) {
        int idx = tid + e * 256;
        int l = idx >> 6;
        int c = idx & 63;
        float acc = 0.0f;
#pragma unroll
        for (int d = 0; d < PHI; d++)
            acc = fmaf(h2S[l][d], w3[d * RHO + c], acc);
        uRaw[l][c] = acc * (1.0f / 9.0f);
    }
    __syncthreads();

    // ---- Phase 0c: diff LUT + bias; Stage A1: horizontal one-hot 3-sums ----
    {
#pragma unroll
        for (int e = 0; e < 2; e++) {
            int idx = tid + e * 256;
            if (idx < 448) {
                int l = idx >> 6;        // 0..6 -> level l+1
                int c = idx & 63;
                uS[l][c] = uRaw[l + 1][c] - uRaw[0][c];
            } else {
                int c = idx - 448;
                biasS[c] = fmaf(9.0f, uRaw[0][c], b3[c]);
            }
        }
        // Stage A1: rows y0-1 .. y0+TY, full width (3 loads + 3 F2I per entry)
        for (int idx = tid; idx < (TY + 2) * TX; idx += 256) {
            int r  = idx / TX;
            int xi = idx - r * TX;           // 0..383 (== global x)
            int yg = y0 - 1 + r;
            uint32_t s;
            if (yg < 0 || yg >= HH) {
                s = 3u;  // three zero-padded pixels -> level-0 one-hots
            } else {
                const float* row = xb + (size_t)yg * WW;
                s = 1u << (4 * (int)(row[xi] * Q_SCALE));
                s += (xi > 0)      ? (1u << (4 * (int)(row[xi - 1] * Q_SCALE))) : 1u;
                s += (xi < WW - 1) ? (1u << (4 * (int)(row[xi + 1] * Q_SCALE))) : 1u;
            }
            rs[r][xi] = s;
        }
    }
    __syncthreads();

    // ---- Stage A2: vertical 3-sums -> packed counts ----
    for (int idx = tid; idx < TY * TX; idx += 256) {
        int r  = idx / TX;
        int xi = idx - r * TX;
        pk[r][xi] = rs[r][xi] + rs[r + 1][xi] + rs[r + 2][xi];
    }

    // ---- Stage B setup: warp = 8 channels, lane = x-quad ----
    const int cg = threadIdx.y;
    const int q  = threadIdx.x;
    const int c8 = cg * 8;

    unsigned long long B2[4];
#pragma unroll
    for (int p = 0; p < 4; p++) {
        const float2 bv = *reinterpret_cast<const float2*>(&biasS[c8 + 2 * p]);
        B2[p] = pack2(bv.x, bv.y);
    }
    __syncthreads();   // pk ready

    float* obase = out + ((size_t)(b * RHO + c8) * HH + y0) * WW + 4 * q;
    const size_t plane = (size_t)HH * WW;

    // ---- Stage B: levels-outer, LUT broadcast from SMEM; 3 x-segments/row ----
#pragma unroll 1
    for (int ty = 0; ty < TY; ty++) {
        float* orow = obase + (size_t)ty * WW;
#pragma unroll 1
        for (int seg = 0; seg < 3; seg++) {
            const int xoff = seg * 128;
            uint32_t pv[4];
#pragma unroll
            for (int i = 0; i < 4; i++)
                pv[i] = pk[ty][xoff + 4 * q + i];

            unsigned long long acc[4][4];   // [pixel][pair]
#pragma unroll
            for (int l = 0; l < 7; l++) {
                unsigned long long Ul[4];
#pragma unroll
                for (int p = 0; p < 4; p++) {
                    const float2 uv = *reinterpret_cast<const float2*>(&uS[l][c8 + 2 * p]);
                    Ul[p] = pack2(uv.x, uv.y);
                }
#pragma unroll
                for (int i = 0; i < 4; i++) {
                    uint32_t bits = ((pv[i] >> (4 * (l + 1))) & 0xFu) | 0x4B000000u;
                    unsigned long long md = pack_dup(__uint_as_float(bits) - 8388608.0f);
                    if (l == 0) {
#pragma unroll
                        for (int p = 0; p < 4; p++)
                            acc[i][p] = ffma2(md, Ul[p], B2[p]);
                    } else {
#pragma unroll
                        for (int p = 0; p < 4; p++)
                            acc[i][p] = ffma2(md, Ul[p], acc[i][p]);
                    }
                }
            }

            // ReLU + streaming float4 stores: 512B contiguous per warp,
            // 3 consecutive segments -> 1536B contiguous per plane-row.
#pragma unroll
            for (int p = 0; p < 4; p++) {
                float lo0, hi0, lo1, hi1, lo2, hi2, lo3, hi3;
                unpack2(acc[0][p], lo0, hi0);
                unpack2(acc[1][p], lo1, hi1);
                unpack2(acc[2][p], lo2, hi2);
                unpack2(acc[3][p], lo3, hi3);
                float4 v0 = make_float4(fmaxf(lo0, 0.0f), fmaxf(lo1, 0.0f),
                                        fmaxf(lo2, 0.0f), fmaxf(lo3, 0.0f));
                float4 v1 = make_float4(fmaxf(hi0, 0.0f), fmaxf(hi1, 0.0f),
                                        fmaxf(hi2, 0.0f), fmaxf(hi3, 0.0f));
                __stcs(reinterpret_cast<float4*>(orow + (size_t)(2 * p) * plane + xoff), v0);
                __stcs(reinterpret_cast<float4*>(orow + (size_t)(2 * p + 1) * plane + xoff), v1);
            }
        }
    }
}

// ---------------------------------------------------------------------------
// Harness entry point
// ---------------------------------------------------------------------------
extern "C" void kernel_launch(void* const* d_in, const int* in_sizes, int n_in,
                              void* d_out, int out_size) {
    const float* x  = (const float*)d_in[0];
    const float* w1 = (const float*)d_in[1];
    const float* b1 = (const float*)d_in[2];
    const float* w2 = (const float*)d_in[3];
    const float* b2 = (const float*)d_in[4];
    const float* w3 = (const float*)d_in[5];
    const float* b3 = (const float*)d_in[6];
    float* out = (float*)d_out;

    dim3 grid(HH / TY, BATCH);   // (48, 8) = 384 blocks -> single resident wave
    dim3 blk(32, 8);
    lpmp_fused<<<grid, blk>>>(x, w1, b1, w2, b2, w3, b3, out);
}

// round 13
// speedup vs baseline: 1.2024x; 1.2024x over previous
#include <cuda_runtime.h>
#include <cstdint>

// Problem constants
#define BATCH 8
#define HH 384
#define WW 384
#define PHI 32
#define RHO 64
#define Q_SCALE (255.0f / 32.0f)

#define TY 8
#define TX 128

// ---------------------------------------------------------------------------
// f32x2 packed helpers (sm_103a)
// ---------------------------------------------------------------------------
__device__ __forceinline__ unsigned long long ffma2(unsigned long long a,
                                                    unsigned long long b,
                                                    unsigned long long c) {
    unsigned long long d;
    asm("fma.rn.f32x2 %0, %1, %2, %3;" : "=l"(d) : "l"(a), "l"(b), "l"(c));
    return d;
}
__device__ __forceinline__ unsigned long long pack_dup(float v) {
    unsigned long long d;
    asm("mov.b64 %0, {%1, %1};" : "=l"(d) : "f"(v));
    return d;
}
__device__ __forceinline__ unsigned long long pack2(float lo, float hi) {
    unsigned long long d;
    asm("mov.b64 %0, {%1, %2};" : "=l"(d) : "f"(lo), "f"(hi));
    return d;
}
__device__ __forceinline__ void unpack2(unsigned long long a, float& lo, float& hi) {
    asm("mov.b64 {%0, %1}, %2;" : "=f"(lo), "=f"(hi) : "l"(a));
}

// ---------------------------------------------------------------------------
// Champion kernel (R8 configuration — write-bandwidth-roofline bound).
//
// Math: q = floor(x*255/32) in {0..7}; the per-neighbor MLP + rho collapse to
// an 8x64 LUT u[l][c] = ((relu(l*w1+b1) @ w2 + b2) @ w3) / 9.
// With 3x3 level counts n_l (sum = 9, zero-padding = level 0):
//   out[c] = relu( sum_{l=1..7} n_l * d_l[c] + bias[c] ),
//     d_l = u[l]-u[0],  bias = b3 + 9*u[0].
// Count->float: bits (n | 0x4B000000) = 2^23 + n, subtract 2^23 (exact).
//
// Stage A: per-pixel one-hot nibble words, separable 3-sums (horiz then vert).
// Stage B: levels-outer FFMA2 with the diff-LUT broadcast from SMEM (keeps
// regs at 80 -> 3 CTAs/SM); warp = 8 channels, lane = x-quad -> every STG.128
// is 512B contiguous per warp; streaming (.cs) stores.
// ---------------------------------------------------------------------------
__global__ __launch_bounds__(256, 3)
void lpmp_fused(const float* __restrict__ x,
                const float* __restrict__ w1, const float* __restrict__ b1,
                const float* __restrict__ w2, const float* __restrict__ b2,
                const float* __restrict__ w3, const float* __restrict__ b3,
                float* __restrict__ out) {
    __shared__ float h2S[8][PHI];        // hidden layer per level
    __shared__ float uRaw[8][RHO];       // raw LUT
    __shared__ float uS[7][RHO];         // u[l]-u[0]
    __shared__ float biasS[RHO];         // b3 + 9*u[0]
    __shared__ uint32_t rs[TY + 2][TX];  // horizontal one-hot 3-sums
    __shared__ uint32_t pk[TY][TX];      // 3x3 packed nibble counts

    const int x0 = blockIdx.x * TX;
    const int y0 = blockIdx.y * TY;
    const int b  = blockIdx.z;
    const int tid = threadIdx.y * 32 + threadIdx.x;
    const float* xb = x + (size_t)b * HH * WW;

    // ---- Phase 0a: h2[l][d] = b2[d] + sum_j relu(l*w1[j]+b1[j]) * w2[j][d] ----
    {
        int l = tid >> 5;            // 0..7
        int d = tid & 31;            // 0..31
        float acc = b2[d];
        float lf = (float)l;
#pragma unroll
        for (int j = 0; j < PHI; j++) {
            float h1 = fmaxf(fmaf(lf, w1[j], b1[j]), 0.0f);
            acc = fmaf(h1, w2[j * PHI + d], acc);
        }
        h2S[l][d] = acc;
    }
    __syncthreads();

    // ---- Phase 0b: uRaw[l][c] = (h2[l] . w3[:,c]) / 9, 512 entries ----
#pragma unroll
    for (int e = 0; e < 2; e++) {
        int idx = tid + e * 256;
        int l = idx >> 6;            // 0..7
        int c = idx & 63;            // 0..63
        float acc = 0.0f;
#pragma unroll
        for (int d = 0; d < PHI; d++)
            acc = fmaf(h2S[l][d], w3[d * RHO + c], acc);
        uRaw[l][c] = acc * (1.0f / 9.0f);
    }
    __syncthreads();

    // ---- Phase 0c: diff LUT + bias; Stage A1: horizontal one-hot 3-sums ----
    {
#pragma unroll
        for (int e = 0; e < 2; e++) {
            int idx = tid + e * 256;
            if (idx < 448) {
                int l = idx >> 6;        // 0..6 -> level l+1
                int c = idx & 63;
                uS[l][c] = uRaw[l + 1][c] - uRaw[0][c];
            } else {
                int c = idx - 448;
                biasS[c] = fmaf(9.0f, uRaw[0][c], b3[c]);
            }
        }
        // Stage A1: rows y0-1 .. y0+TY
        for (int idx = tid; idx < (TY + 2) * TX; idx += 256) {
            int r  = idx / TX;
            int xi = idx - r * TX;
            int yg = y0 - 1 + r;
            int xg = x0 + xi;
            uint32_t s;
            if (yg < 0 || yg >= HH) {
                s = 3u;  // three zero-padded pixels -> level-0 one-hots
            } else {
                const float* row = xb + (size_t)yg * WW;
                s = 1u << (4 * (int)(row[xg] * Q_SCALE));
                int xl = xg - 1;
                s += (xl >= 0) ? (1u << (4 * (int)(row[xl] * Q_SCALE))) : 1u;
                int xr = xg + 1;
                s += (xr < WW) ? (1u << (4 * (int)(row[xr] * Q_SCALE))) : 1u;
            }
            rs[r][xi] = s;
        }
    }
    __syncthreads();

    // ---- Stage A2: vertical 3-sums -> packed counts ----
    for (int idx = tid; idx < TY * TX; idx += 256) {
        int r  = idx / TX;
        int xi = idx - r * TX;
        pk[r][xi] = rs[r][xi] + rs[r + 1][xi] + rs[r + 2][xi];
    }

    // ---- Stage B setup: warp = 8 channels, lane = x-quad ----
    const int cg = threadIdx.y;   // channel group: channels cg*8 .. cg*8+7
    const int q  = threadIdx.x;   // x-quad: pixels x0+4q .. x0+4q+3
    const int c8 = cg * 8;

    unsigned long long B2[4];     // bias pairs, kept in regs (loaded once)
#pragma unroll
    for (int p = 0; p < 4; p++) {
        const float2 bv = *reinterpret_cast<const float2*>(&biasS[c8 + 2 * p]);
        B2[p] = pack2(bv.x, bv.y);
    }
    __syncthreads();   // pk ready

    const int xbase = x0 + 4 * q;
    float* obase = out + ((size_t)(b * RHO + c8) * HH + y0) * WW + xbase;
    const size_t plane = (size_t)HH * WW;

    // ---- Stage B: levels-outer, LUT streamed from SMEM (broadcast LDS) ----
#pragma unroll 1
    for (int ty = 0; ty < TY; ty++) {
        uint32_t pv[4];
#pragma unroll
        for (int i = 0; i < 4; i++)
            pv[i] = pk[ty][4 * q + i];

        unsigned long long acc[4][4];   // [pixel][pair]
#pragma unroll
        for (int l = 0; l < 7; l++) {
            unsigned long long Ul[4];
#pragma unroll
            for (int p = 0; p < 4; p++) {
                const float2 uv = *reinterpret_cast<const float2*>(&uS[l][c8 + 2 * p]);
                Ul[p] = pack2(uv.x, uv.y);
            }
#pragma unroll
            for (int i = 0; i < 4; i++) {
                uint32_t bits = ((pv[i] >> (4 * (l + 1))) & 0xFu) | 0x4B000000u;
                unsigned long long md = pack_dup(__uint_as_float(bits) - 8388608.0f);
                if (l == 0) {
#pragma unroll
                    for (int p = 0; p < 4; p++)
                        acc[i][p] = ffma2(md, Ul[p], B2[p]);
                } else {
#pragma unroll
                    for (int p = 0; p < 4; p++)
                        acc[i][p] = ffma2(md, Ul[p], acc[i][p]);
                }
            }
        }

        // ReLU + streaming float4 stores: 512B contiguous per warp per plane-row
        float* orow = obase + (size_t)ty * WW;
#pragma unroll
        for (int p = 0; p < 4; p++) {
            float lo0, hi0, lo1, hi1, lo2, hi2, lo3, hi3;
            unpack2(acc[0][p], lo0, hi0);
            unpack2(acc[1][p], lo1, hi1);
            unpack2(acc[2][p], lo2, hi2);
            unpack2(acc[3][p], lo3, hi3);
            float4 v0 = make_float4(fmaxf(lo0, 0.0f), fmaxf(lo1, 0.0f),
                                    fmaxf(lo2, 0.0f), fmaxf(lo3, 0.0f));
            float4 v1 = make_float4(fmaxf(hi0, 0.0f), fmaxf(hi1, 0.0f),
                                    fmaxf(hi2, 0.0f), fmaxf(hi3, 0.0f));
            __stcs(reinterpret_cast<float4*>(orow + (size_t)(2 * p) * plane), v0);
            __stcs(reinterpret_cast<float4*>(orow + (size_t)(2 * p + 1) * plane), v1);
        }
    }
}

// ---------------------------------------------------------------------------
// Harness entry point
// ---------------------------------------------------------------------------
extern "C" void kernel_launch(void* const* d_in, const int* in_sizes, int n_in,
                              void* d_out, int out_size) {
    const float* x  = (const float*)d_in[0];
    const float* w1 = (const float*)d_in[1];
    const float* b1 = (const float*)d_in[2];
    const float* w2 = (const float*)d_in[3];
    const float* b2 = (const float*)d_in[4];
    const float* w3 = (const float*)d_in[5];
    const float* b3 = (const float*)d_in[6];
    float* out = (float*)d_out;

    dim3 grid(WW / TX, HH / TY, BATCH);   // (3, 48, 8) = 1152 blocks
    dim3 blk(32, 8);
    lpmp_fused<<<grid, blk>>>(x, w1, b1, w2, b2, w3, b3, out);
}

// round 14
// speedup vs baseline: 1.2031x; 1.0006x over previous
#include <cuda_runtime.h>
#include <cstdint>

// Problem constants
#define BATCH 8
#define HH 384
#define WW 384
#define PHI 32
#define RHO 64
#define Q_SCALE (255.0f / 32.0f)

#define TY 8
#define TX 128

// ---------------------------------------------------------------------------
// f32x2 packed helpers (sm_103a)
// ---------------------------------------------------------------------------
__device__ __forceinline__ unsigned long long ffma2(unsigned long long a,
                                                    unsigned long long b,
                                                    unsigned long long c) {
    unsigned long long d;
    asm("fma.rn.f32x2 %0, %1, %2, %3;" : "=l"(d) : "l"(a), "l"(b), "l"(c));
    return d;
}
__device__ __forceinline__ unsigned long long pack_dup(float v) {
    unsigned long long d;
    asm("mov.b64 %0, {%1, %1};" : "=l"(d) : "f"(v));
    return d;
}
__device__ __forceinline__ unsigned long long pack2(float lo, float hi) {
    unsigned long long d;
    asm("mov.b64 %0, {%1, %2};" : "=l"(d) : "f"(lo), "f"(hi));
    return d;
}
__device__ __forceinline__ void unpack2(unsigned long long a, float& lo, float& hi) {
    asm("mov.b64 {%0, %1}, %2;" : "=f"(lo), "=f"(hi) : "l"(a));
}

// ---------------------------------------------------------------------------
// Final champion kernel — write-bandwidth-roofline bound (5.84 TB/s sustained).
//
// Math: q = floor(x*255/32) in {0..7} (x ~ U[0,1)); the per-neighbor MLP phi
// and the rho projection collapse to an 8x64 LUT
//   u[l][c] = ((relu(l*w1+b1) @ w2 + b2) @ w3) / 9.
// With 3x3 level counts n_l (sum = 9, zero-padding = level 0):
//   out[c] = relu( sum_{l=1..7} n_l * d_l[c] + bias[c] ),
//     d_l = u[l]-u[0],  bias = b3 + 9*u[0].
// Count->float: bits (n | 0x4B000000) = 2^23 + n, subtract 2^23 (exact).
//
// Stage A: per-pixel one-hot nibble words, separable 3-sums (horiz then vert).
// Stage B: levels-outer FFMA2 with the diff-LUT broadcast from SMEM (keeps
// regs at 80 -> 3 CTAs/SM); warp = 8 channels, lane = x-quad -> every STG.128
// is 512B contiguous per warp; streaming (.cs) stores.
// ---------------------------------------------------------------------------
__global__ __launch_bounds__(256, 3)
void lpmp_fused(const float* __restrict__ x,
                const float* __restrict__ w1, const float* __restrict__ b1,
                const float* __restrict__ w2, const float* __restrict__ b2,
                const float* __restrict__ w3, const float* __restrict__ b3,
                float* __restrict__ out) {
    __shared__ float h2S[8][PHI];        // hidden layer per level
    __shared__ float uRaw[8][RHO];       // raw LUT
    __shared__ float uS[7][RHO];         // u[l]-u[0]
    __shared__ float biasS[RHO];         // b3 + 9*u[0]
    __shared__ uint32_t rs[TY + 2][TX];  // horizontal one-hot 3-sums
    __shared__ uint32_t pk[TY][TX];      // 3x3 packed nibble counts

    const int x0 = blockIdx.x * TX;
    const int y0 = blockIdx.y * TY;
    const int b  = blockIdx.z;
    const int tid = threadIdx.y * 32 + threadIdx.x;
    const float* xb = x + (size_t)b * HH * WW;

    // ---- Phase 0a: h2[l][d] = b2[d] + sum_j relu(l*w1[j]+b1[j]) * w2[j][d] ----
    {
        int l = tid >> 5;            // 0..7
        int d = tid & 31;            // 0..31
        float acc = b2[d];
        float lf = (float)l;
#pragma unroll
        for (int j = 0; j < PHI; j++) {
            float h1 = fmaxf(fmaf(lf, w1[j], b1[j]), 0.0f);
            acc = fmaf(h1, w2[j * PHI + d], acc);
        }
        h2S[l][d] = acc;
    }
    __syncthreads();

    // ---- Phase 0b: uRaw[l][c] = (h2[l] . w3[:,c]) / 9, 512 entries ----
#pragma unroll
    for (int e = 0; e < 2; e++) {
        int idx = tid + e * 256;
        int l = idx >> 6;            // 0..7
        int c = idx & 63;            // 0..63
        float acc = 0.0f;
#pragma unroll
        for (int d = 0; d < PHI; d++)
            acc = fmaf(h2S[l][d], w3[d * RHO + c], acc);
        uRaw[l][c] = acc * (1.0f / 9.0f);
    }
    __syncthreads();

    // ---- Phase 0c: diff LUT + bias; Stage A1: horizontal one-hot 3-sums ----
    {
#pragma unroll
        for (int e = 0; e < 2; e++) {
            int idx = tid + e * 256;
            if (idx < 448) {
                int l = idx >> 6;        // 0..6 -> level l+1
                int c = idx & 63;
                uS[l][c] = uRaw[l + 1][c] - uRaw[0][c];
            } else {
                int c = idx - 448;
                biasS[c] = fmaf(9.0f, uRaw[0][c], b3[c]);
            }
        }
        // Stage A1: rows y0-1 .. y0+TY
        for (int idx = tid; idx < (TY + 2) * TX; idx += 256) {
            int r  = idx / TX;
            int xi = idx - r * TX;
            int yg = y0 - 1 + r;
            int xg = x0 + xi;
            uint32_t s;
            if (yg < 0 || yg >= HH) {
                s = 3u;  // three zero-padded pixels -> level-0 one-hots
            } else {
                const float* row = xb + (size_t)yg * WW;
                s = 1u << (4 * (int)(row[xg] * Q_SCALE));
                int xl = xg - 1;
                s += (xl >= 0) ? (1u << (4 * (int)(row[xl] * Q_SCALE))) : 1u;
                int xr = xg + 1;
                s += (xr < WW) ? (1u << (4 * (int)(row[xr] * Q_SCALE))) : 1u;
            }
            rs[r][xi] = s;
        }
    }
    __syncthreads();

    // ---- Stage A2: vertical 3-sums -> packed counts ----
    for (int idx = tid; idx < TY * TX; idx += 256) {
        int r  = idx / TX;
        int xi = idx - r * TX;
        pk[r][xi] = rs[r][xi] + rs[r + 1][xi] + rs[r + 2][xi];
    }

    // ---- Stage B setup: warp = 8 channels, lane = x-quad ----
    const int cg = threadIdx.y;   // channel group: channels cg*8 .. cg*8+7
    const int q  = threadIdx.x;   // x-quad: pixels x0+4q .. x0+4q+3
    const int c8 = cg * 8;

    unsigned long long B2[4];     // bias pairs, kept in regs (loaded once)
#pragma unroll
    for (int p = 0; p < 4; p++) {
        const float2 bv = *reinterpret_cast<const float2*>(&biasS[c8 + 2 * p]);
        B2[p] = pack2(bv.x, bv.y);
    }
    __syncthreads();   // pk ready

    const int xbase = x0 + 4 * q;
    float* obase = out + ((size_t)(b * RHO + c8) * HH + y0) * WW + xbase;
    const size_t plane = (size_t)HH * WW;

    // ---- Stage B: levels-outer, LUT streamed from SMEM (broadcast LDS) ----
#pragma unroll 1
    for (int ty = 0; ty < TY; ty++) {
        uint32_t pv[4];
#pragma unroll
        for (int i = 0; i < 4; i++)
            pv[i] = pk[ty][4 * q + i];

        unsigned long long acc[4][4];   // [pixel][pair]
#pragma unroll
        for (int l = 0; l < 7; l++) {
            unsigned long long Ul[4];
#pragma unroll
            for (int p = 0; p < 4; p++) {
                const float2 uv = *reinterpret_cast<const float2*>(&uS[l][c8 + 2 * p]);
                Ul[p] = pack2(uv.x, uv.y);
            }
#pragma unroll
            for (int i = 0; i < 4; i++) {
                uint32_t bits = ((pv[i] >> (4 * (l + 1))) & 0xFu) | 0x4B000000u;
                unsigned long long md = pack_dup(__uint_as_float(bits) - 8388608.0f);
                if (l == 0) {
#pragma unroll
                    for (int p = 0; p < 4; p++)
                        acc[i][p] = ffma2(md, Ul[p], B2[p]);
                } else {
#pragma unroll
                    for (int p = 0; p < 4; p++)
                        acc[i][p] = ffma2(md, Ul[p], acc[i][p]);
                }
            }
        }

        // ReLU + streaming float4 stores: 512B contiguous per warp per plane-row
        float* orow = obase + (size_t)ty * WW;
#pragma unroll
        for (int p = 0; p < 4; p++) {
            float lo0, hi0, lo1, hi1, lo2, hi2, lo3, hi3;
            unpack2(acc[0][p], lo0, hi0);
            unpack2(acc[1][p], lo1, hi1);
            unpack2(acc[2][p], lo2, hi2);
            unpack2(acc[3][p], lo3, hi3);
            float4 v0 = make_float4(fmaxf(lo0, 0.0f), fmaxf(lo1, 0.0f),
                                    fmaxf(lo2, 0.0f), fmaxf(lo3, 0.0f));
            float4 v1 = make_float4(fmaxf(hi0, 0.0f), fmaxf(hi1, 0.0f),
                                    fmaxf(hi2, 0.0f), fmaxf(hi3, 0.0f));
            __stcs(reinterpret_cast<float4*>(orow + (size_t)(2 * p) * plane), v0);
            __stcs(reinterpret_cast<float4*>(orow + (size_t)(2 * p + 1) * plane), v1);
        }
    }
}

// ---------------------------------------------------------------------------
// Harness entry point
// ---------------------------------------------------------------------------
extern "C" void kernel_launch(void* const* d_in, const int* in_sizes, int n_in,
                              void* d_out, int out_size) {
    const float* x  = (const float*)d_in[0];
    const float* w1 = (const float*)d_in[1];
    const float* b1 = (const float*)d_in[2];
    const float* w2 = (const float*)d_in[3];
    const float* b2 = (const float*)d_in[4];
    const float* w3 = (const float*)d_in[5];
    const float* b3 = (const float*)d_in[6];
    float* out = (float*)d_out;

    dim3 grid(WW / TX, HH / TY, BATCH);   // (3, 48, 8) = 1152 blocks
    dim3 blk(32, 8);
    lpmp_fused<<<grid, blk>>>(x, w1, b1, w2, b2, w3, b3, out);
}